// round 6
// baseline (speedup 1.0000x reference)
#include <cuda_runtime.h>
#include <cstdint>

#define NN    50000
#define D     128
#define NK    4
#define NT    2
#define NE    100000
#define NOHL  3
#define KD1   (D + NOHL)     // 131
#define AST   132            // transposed-tile row stride (floats)
#define TILE  128
#define NTHR  512

// smem layouts (floats)
#define FUSED_AS   (KD1 * AST)          // 17292
#define FUSED_BS   (D * AST)            // 16896
#define FUSED_BUF  (KD1 * 64)           // 8384
#define SM_FUSED   ((FUSED_AS + FUSED_BS + 2 * FUSED_BUF) * 4)   // 203824 B
#define LIN_AS     (D * AST)
#define LIN_BUF    (D * 64)
#define SM_LIN     ((LIN_AS + 2 * LIN_BUF) * 4)                  // 133120 B

typedef unsigned long long ull;

static __device__ __forceinline__ float fsig(float x) {
    return 1.0f / (1.0f + __expf(-x));
}
static __device__ __forceinline__ ull dup2(float v) {
    ull r; asm("mov.b64 %0, {%1, %1};" : "=l"(r) : "f"(v)); return r;
}
static __device__ __forceinline__ void upk2(ull v, float &lo, float &hi) {
    asm("mov.b64 {%0, %1}, %2;" : "=f"(lo), "=f"(hi) : "l"(v));
}
static __device__ __forceinline__ ull ffma2(ull a, ull b, ull c) {
    ull d; asm("fma.rn.f32x2 %0, %1, %2, %3;" : "=l"(d) : "l"(a), "l"(b), "l"(c));
    return d;
}
static __device__ __forceinline__ void cp16(unsigned s, const void* g) {
    asm volatile("cp.async.cg.shared.global [%0], [%1], 16;" :: "r"(s), "l"(g));
}
static __device__ __forceinline__ void cp_commit() {
    asm volatile("cp.async.commit_group;" ::: "memory");
}
static __device__ __forceinline__ void cp_wait0() {
    asm volatile("cp.async.wait_group 0;" ::: "memory");
}

// Copy a 64-col half of a [KD][128] row-major weight into smem [KD][64].
// One 64-float row = 16 x 16B chunks.  (R4 bug: used 4 chunks/row.)
static __device__ __forceinline__ void fill_half(float* dst, const float* __restrict__ W,
                                                 int half, int KD, int tid)
{
    const unsigned d0 = (unsigned)__cvta_generic_to_shared(dst);
    const int n = KD * 16;                      // 16B chunks total
    for (int i = tid; i < n; i += NTHR) {
        const int kk = i >> 4, c = i & 15;
        cp16(d0 + (unsigned)(kk * 64 + c * 4) * 4u, W + kk * D + half * 64 + c * 4);
    }
    cp_commit();
}

// ---------------------------------------------------------------------------
// 64-col GEMM pass over transposed+swizzled A tile.
//   A element (kdim kk, row r) at A[kk*AST + (r ^ (((kk>>3)&7)<<2))].
//   Wh: [KD][64] smem half. Thread: rows rr..rr+7 (rr = warp*8, warp-uniform
//   -> broadcast A loads), cols {2*lane, 2*lane+1} in the half.
//   acc[rp][q]: lo = row rr+2rp, hi = row rr+2rp+1, col 2*lane+q.
// ---------------------------------------------------------------------------
template<int KD>
static __device__ __forceinline__ void gemm_pass(const float* __restrict__ A,
                                                 const float* __restrict__ Wh,
                                                 ull (&acc)[4][2], int rr, int lane)
{
    #pragma unroll
    for (int rp = 0; rp < 4; ++rp) { acc[rp][0] = 0ull; acc[rp][1] = 0ull; }

    #pragma unroll 4
    for (int kk = 0; kk < KD; ++kk) {
        const int s4 = ((kk >> 3) & 7) << 2;
        const float* Ar = A + kk * AST;
        const ulonglong2 alo = *(const ulonglong2*)(Ar + (rr ^ s4));
        const ulonglong2 ahi = *(const ulonglong2*)(Ar + ((rr + 4) ^ s4));
        const float2 b = *(const float2*)(Wh + kk * 64 + 2 * lane);
        const ull b0 = dup2(b.x), b1 = dup2(b.y);
        const ull ap[4] = {alo.x, alo.y, ahi.x, ahi.y};
        #pragma unroll
        for (int rp = 0; rp < 4; ++rp) {
            acc[rp][0] = ffma2(ap[rp], b0, acc[rp][0]);
            acc[rp][1] = ffma2(ap[rp], b1, acc[rp][1]);
        }
    }
}

// gather one 128-row tile of h into transposed/swizzled As. 4 threads/row.
static __device__ __forceinline__ void gather_rows(float* As, const float* __restrict__ h,
                                                   int row, int r, int sub)
{
    if (row >= 0) {
        const float4* hrow = (const float4*)(h + (size_t)row * D) + 8 * sub;
        #pragma unroll
        for (int q = 0; q < 8; ++q) {
            const float4 v = hrow[q];
            const int c  = 32 * sub + 4 * q;
            const int pr = r ^ (((c >> 3) & 7) << 2);
            float* dst = As + c * AST + pr;
            dst[0] = v.x; dst[AST] = v.y; dst[2 * AST] = v.z; dst[3 * AST] = v.w;
        }
    } else {
        #pragma unroll
        for (int q = 0; q < 8; ++q) {
            const int c  = 32 * sub + 4 * q;
            const int pr = r ^ (((c >> 3) & 7) << 2);
            float* dst = As + c * AST + pr;
            dst[0] = 0.f; dst[AST] = 0.f; dst[2 * AST] = 0.f; dst[3 * AST] = 0.f;
        }
    }
}

// prod[j][2h+q] *= sigmoid(acc + bias), pass half h.
static __device__ __forceinline__ void prod_sig(const ull (&acc)[4][2],
                                                float (&prod)[8][4],
                                                const float* __restrict__ bias,
                                                int lane, int h)
{
    const float2 bb = *(const float2*)(bias + 64 * h + 2 * lane);
    #pragma unroll
    for (int rp = 0; rp < 4; ++rp) {
        float l0, h0, l1, h1;
        upk2(acc[rp][0], l0, h0);
        upk2(acc[rp][1], l1, h1);
        prod[2 * rp][2 * h]         *= fsig(l0 + bb.x);
        prod[2 * rp + 1][2 * h]     *= fsig(h0 + bb.x);
        prod[2 * rp][2 * h + 1]     *= fsig(l1 + bb.y);
        prod[2 * rp + 1][2 * h + 1] *= fsig(h1 + bb.y);
    }
}

// relu(acc + bias) -> transposed/swizzled Bs, pass half h.
static __device__ __forceinline__ void epi_relu(const ull (&acc)[4][2], float* Bs,
                                                const float* __restrict__ bias,
                                                int rr, int lane, int h)
{
    const float2 bb = *(const float2*)(bias + 64 * h + 2 * lane);
    #pragma unroll
    for (int q = 0; q < 2; ++q) {
        const int c  = 64 * h + 2 * lane + q;
        const int s4 = ((c >> 3) & 7) << 2;
        const float bq = q ? bb.y : bb.x;
        float* col = Bs + c * AST;
        #pragma unroll
        for (int rp = 0; rp < 4; ++rp) {
            float lo, hi; upk2(acc[rp][q], lo, hi);
            const int pr = (rr + 2 * rp) ^ s4;
            *(float2*)(col + pr) = make_float2(fmaxf(lo + bq, 0.f), fmaxf(hi + bq, 0.f));
        }
    }
}

// ---------------------------------------------------------------------------
// Kernel 1: h3 = h @ W_lin + b_lin (initializes all of d_out)
// ---------------------------------------------------------------------------
__global__ void __launch_bounds__(NTHR, 1)
gnn_lin_kernel(const float* __restrict__ h, const float* __restrict__ W,
               const float* __restrict__ b, float* __restrict__ out)
{
    extern __shared__ float sm[];
    float* As   = sm;                  // [D][AST]
    float* buf0 = As + LIN_AS;         // [D][64]
    float* buf1 = buf0 + LIN_BUF;

    const int tid  = threadIdx.x;
    const int lane = tid & 31;
    const int rr   = (tid >> 5) * 8;
    const int r0   = blockIdx.x * TILE;

    {
        const int r = tid >> 2, sub = tid & 3;
        const int row = r0 + r;
        gather_rows(As, h, row < NN ? row : -1, r, sub);
    }
    fill_half(buf0, W, 0, D, tid);
    cp_wait0();
    __syncthreads();

    ull acc[4][2];
    #pragma unroll
    for (int hh = 0; hh < 2; ++hh) {
        if (hh == 0) fill_half(buf1, W, 1, D, tid);
        gemm_pass<D>(As, hh ? buf1 : buf0, acc, rr, lane);
        const float2 bb = *(const float2*)(b + 64 * hh + 2 * lane);
        #pragma unroll
        for (int rp = 0; rp < 4; ++rp) {
            float l0, h0, l1, h1;
            upk2(acc[rp][0], l0, h0);
            upk2(acc[rp][1], l1, h1);
            const int row = r0 + rr + 2 * rp;
            if (row < NN)
                *(float2*)(out + (size_t)row * D + 64 * hh + 2 * lane) =
                    make_float2(l0 + bb.x, l1 + bb.y);
            if (row + 1 < NN)
                *(float2*)(out + (size_t)(row + 1) * D + 64 * hh + 2 * lane) =
                    make_float2(h0 + bb.x, h1 + bb.y);
        }
        if (hh == 0) { cp_wait0(); __syncthreads(); }
    }
}

// ---------------------------------------------------------------------------
// Kernel 2: fused per-key message kernel. grid = (ceil(E/128), K)
// ---------------------------------------------------------------------------
__global__ void __launch_bounds__(NTHR, 1)
gnn_fused_kernel(const float* __restrict__ h,
                 const int*   __restrict__ pairs,
                 const float* __restrict__ degrees,
                 const int*   __restrict__ scat,
                 const float* __restrict__ W_tr, const float* __restrict__ b_tr,
                 const float* __restrict__ W_g1, const float* __restrict__ b_g1,
                 const float* __restrict__ W_g2, const float* __restrict__ b_g2,
                 const float* __restrict__ eps,
                 float* __restrict__ out)
{
    extern __shared__ float sm[];
    float* As   = sm;                  // [KD1][AST] gathered ht (transposed/swizzled)
    float* Bs   = As + FUSED_AS;       // [D][AST]   relu(ht@Wg1+b)
    float* buf0 = Bs + FUSED_BS;       // [KD1][64]  weight half (double-buffered)
    float* buf1 = buf0 + FUSED_BUF;

    const int tid  = threadIdx.x;
    const int lane = tid & 31;
    const int rr   = (tid >> 5) * 8;
    const int e0   = blockIdx.x * TILE;
    const int k    = blockIdx.y;

    const float* Wg1 = W_g1 + (size_t)k * KD1 * D;
    const float* Wtr = W_tr + (size_t)k * KD1 * D;
    const float* Wg2 = W_g2 + (size_t)k * D * D;

    float prod[8][4];
    #pragma unroll
    for (int j = 0; j < 8; ++j)
        #pragma unroll
        for (int q = 0; q < 4; ++q) prod[j][q] = 1.0f;

    ull acc[4][2];

    for (int it = 0; it < NT; ++it) {
        __syncthreads();   // prior reads of As/Bs/bufs done
        // gather ht tile
        {
            const int r = tid >> 2, sub = tid & 3;
            const int e = e0 + r;
            int row = -1;
            if (e < NE) row = pairs[(k * NT + it) * NE + e];
            gather_rows(As, h, row, r, sub);
            if (sub == 0) {            // degree features, cols 128..130 (s4 = 0)
                float d0 = 0.f, d1 = 0.f, d2 = 0.f;
                if (e < NE) {
                    const float* dg = degrees + ((size_t)(k * NT + it) * NE + e) * NOHL;
                    d0 = dg[0]; d1 = dg[1]; d2 = dg[2];
                }
                As[(D + 0) * AST + r] = d0;
                As[(D + 1) * AST + r] = d1;
                As[(D + 2) * AST + r] = d2;
            }
        }
        fill_half(buf0, Wg1, 0, KD1, tid);
        cp_wait0();
        __syncthreads();

        // p0: GEMM1 half0 (overlap fill of Wg1 h1)
        fill_half(buf1, Wg1, 1, KD1, tid);
        gemm_pass<KD1>(As, buf0, acc, rr, lane);
        epi_relu(acc, Bs, b_g1 + k * D, rr, lane, 0);
        cp_wait0(); __syncthreads();

        // p1: GEMM1 half1 (overlap fill of Wtr h0)
        fill_half(buf0, Wtr, 0, KD1, tid);
        gemm_pass<KD1>(As, buf1, acc, rr, lane);
        epi_relu(acc, Bs, b_g1 + k * D, rr, lane, 1);
        cp_wait0(); __syncthreads();

        // p2: GEMM2 half0 (overlap fill of Wtr h1)
        fill_half(buf1, Wtr, 1, KD1, tid);
        gemm_pass<KD1>(As, buf0, acc, rr, lane);
        prod_sig(acc, prod, b_tr + k * D, lane, 0);
        cp_wait0(); __syncthreads();

        // p3: GEMM2 half1 (overlap fill of Wg2 h0)
        fill_half(buf0, Wg2, 0, D, tid);
        gemm_pass<KD1>(As, buf1, acc, rr, lane);
        prod_sig(acc, prod, b_tr + k * D, lane, 1);
        cp_wait0(); __syncthreads();

        // p4: GEMM3 half0 over Bs (overlap fill of Wg2 h1)
        fill_half(buf1, Wg2, 1, D, tid);
        gemm_pass<D>(Bs, buf0, acc, rr, lane);
        prod_sig(acc, prod, b_g2 + k * D, lane, 0);
        cp_wait0(); __syncthreads();

        // p5: GEMM3 half1 over Bs
        gemm_pass<D>(Bs, buf1, acc, rr, lane);
        prod_sig(acc, prod, b_g2 + k * D, lane, 1);
    }

    // scatter-add: out[scat[k,e]] += (1+eps[k]) * prod
    const float scale = 1.0f + eps[k];
    #pragma unroll
    for (int j = 0; j < 8; ++j) {
        const int e = e0 + rr + j;
        if (e < NE) {
            const int idx = scat[k * NE + e];
            float* dst = out + (size_t)idx * D;
            asm volatile("red.global.add.v2.f32 [%0], {%1,%2};"
                         :: "l"(dst + 2 * lane),
                            "f"(prod[j][0] * scale), "f"(prod[j][1] * scale) : "memory");
            asm volatile("red.global.add.v2.f32 [%0], {%1,%2};"
                         :: "l"(dst + 64 + 2 * lane),
                            "f"(prod[j][2] * scale), "f"(prod[j][3] * scale) : "memory");
        }
    }
}

// ---------------------------------------------------------------------------
extern "C" void kernel_launch(void* const* d_in, const int* in_sizes, int n_in,
                              void* d_out, int out_size)
{
    const float* h       = (const float*)d_in[0];
    const int*   pairs   = (const int*)  d_in[1];
    const float* degrees = (const float*)d_in[2];
    const int*   scat    = (const int*)  d_in[3];
    const float* W_lin   = (const float*)d_in[4];
    const float* b_lin   = (const float*)d_in[5];
    const float* W_tr    = (const float*)d_in[6];
    const float* b_tr    = (const float*)d_in[7];
    const float* W_g1    = (const float*)d_in[8];
    const float* b_g1    = (const float*)d_in[9];
    const float* W_g2    = (const float*)d_in[10];
    const float* b_g2    = (const float*)d_in[11];
    const float* eps     = (const float*)d_in[12];
    float* out = (float*)d_out;

    cudaFuncSetAttribute(gnn_lin_kernel,
                         cudaFuncAttributeMaxDynamicSharedMemorySize, SM_LIN);
    cudaFuncSetAttribute(gnn_fused_kernel,
                         cudaFuncAttributeMaxDynamicSharedMemorySize, SM_FUSED);

    gnn_lin_kernel<<<(NN + TILE - 1) / TILE, NTHR, SM_LIN>>>(h, W_lin, b_lin, out);

    dim3 grid((NE + TILE - 1) / TILE, NK);
    gnn_fused_kernel<<<grid, NTHR, SM_FUSED>>>(h, pairs, degrees, scat,
                                               W_tr, b_tr, W_g1, b_g1,
                                               W_g2, b_g2, eps, out);
}

// round 8
// speedup vs baseline: 1.2361x; 1.2361x over previous
#include <cuda_runtime.h>
#include <cstdint>

#define NN    50000
#define D     128
#define NK    4
#define NT    2
#define NE    100000
#define NOHL  3
#define KD1   (D + NOHL)     // 131
#define KH0   66
#define KH1   65

// ---- fused kernel geometry: 64-row tiles, 256 threads, 2 CTAs/SM ----
#define TR    64             // pair rows per fused CTA
#define AST2  68             // fused As row stride (floats)
#define FTHR  256
#define F_AS  (KD1 * AST2)   // 8908 floats
#define F_BUF (KH0 * D)      // 8448 floats
#define SM_F  ((F_AS + 2 * F_BUF) * 4)   // 103216 B

// ---- lin kernel geometry (R6-proven): 128-row tiles, 512 threads ----
#define LTILE 128
#define LAST  132
#define LTHR  512
#define L_AS  (D * LAST)
#define L_BUF (D * 64)
#define SM_L  ((L_AS + 2 * L_BUF) * 4)   // 133120 B

typedef unsigned long long ull;

static __device__ __forceinline__ float fsig(float x) {
    return 1.0f / (1.0f + __expf(-x));
}
static __device__ __forceinline__ ull dup2(float v) {
    ull r; asm("mov.b64 %0, {%1, %1};" : "=l"(r) : "f"(v)); return r;
}
static __device__ __forceinline__ void upk2(ull v, float &lo, float &hi) {
    asm("mov.b64 {%0, %1}, %2;" : "=f"(lo), "=f"(hi) : "l"(v));
}
static __device__ __forceinline__ ull ffma2(ull a, ull b, ull c) {
    ull d; asm("fma.rn.f32x2 %0, %1, %2, %3;" : "=l"(d) : "l"(a), "l"(b), "l"(c));
    return d;
}
static __device__ __forceinline__ void cp16(unsigned s, const void* g) {
    asm volatile("cp.async.cg.shared.global [%0], [%1], 16;" :: "r"(s), "l"(g));
}
static __device__ __forceinline__ void cp_commit() {
    asm volatile("cp.async.commit_group;" ::: "memory");
}
static __device__ __forceinline__ void cp_wait0() {
    asm volatile("cp.async.wait_group 0;" ::: "memory");
}

// gather one tile row of h into transposed/swizzled As (stride STR). 4 thr/row.
template<int STR>
static __device__ __forceinline__ void gather_rows(float* As, const float* __restrict__ h,
                                                   int row, int r, int sub)
{
    if (row >= 0) {
        const float4* hrow = (const float4*)(h + (size_t)row * D) + 8 * sub;
        #pragma unroll
        for (int q = 0; q < 8; ++q) {
            const float4 v = hrow[q];
            const int c  = 32 * sub + 4 * q;
            const int pr = r ^ (((c >> 3) & 7) << 2);
            float* dst = As + c * STR + pr;
            dst[0] = v.x; dst[STR] = v.y; dst[2 * STR] = v.z; dst[3 * STR] = v.w;
        }
    } else {
        #pragma unroll
        for (int q = 0; q < 8; ++q) {
            const int c  = 32 * sub + 4 * q;
            const int pr = r ^ (((c >> 3) & 7) << 2);
            float* dst = As + c * STR + pr;
            dst[0] = 0.f; dst[STR] = 0.f; dst[2 * STR] = 0.f; dst[3 * STR] = 0.f;
        }
    }
}

// ============================ fused kernel helpers ============================

// contiguous weight rows [k0, k0+KH) of a [*][128] matrix -> smem [KH][128]
static __device__ __forceinline__ void fillw(float* dst, const float* __restrict__ W,
                                             int k0, int KH, int tid)
{
    const unsigned d0 = (unsigned)__cvta_generic_to_shared(dst);
    const char* src = (const char*)(W + (size_t)k0 * D);
    const int n = KH * 32;                       // 16B chunks (32 per 128-float row)
    for (int i = tid; i < n; i += FTHR)
        cp16(d0 + (unsigned)i * 16u, src + (size_t)i * 16);
    cp_commit();
}

static __device__ __forceinline__ void zacc(ull (&acc)[4][4]) {
    #pragma unroll
    for (int rp = 0; rp < 4; ++rp)
        #pragma unroll
        for (int q = 0; q < 4; ++q) acc[rp][q] = 0ull;
}

// partial-K GEMM pass: A transposed/swizzled [131][AST2], Wh [KH][128] smem.
// Thread: rows rr..rr+7 (rr warp-uniform), cols 4*lane..4*lane+3.
template<int KH>
static __device__ __forceinline__ void fgemm(const float* __restrict__ As,
                                             const float* __restrict__ Wh,
                                             int k0, ull (&acc)[4][4],
                                             int rr, int lane)
{
    #pragma unroll 4
    for (int kk = 0; kk < KH; ++kk) {
        const int kg = k0 + kk;
        const int s4 = ((kg >> 3) & 7) << 2;
        const float* Ar = As + kg * AST2;
        const ulonglong2 alo = *(const ulonglong2*)(Ar + (rr ^ s4));
        const ulonglong2 ahi = *(const ulonglong2*)(Ar + ((rr + 4) ^ s4));
        const float4 b = *(const float4*)(Wh + kk * D + 4 * lane);
        const ull b0 = dup2(b.x), b1 = dup2(b.y), b2 = dup2(b.z), b3 = dup2(b.w);
        const ull ap[4] = {alo.x, alo.y, ahi.x, ahi.y};
        #pragma unroll
        for (int rp = 0; rp < 4; ++rp) {
            acc[rp][0] = ffma2(ap[rp], b0, acc[rp][0]);
            acc[rp][1] = ffma2(ap[rp], b1, acc[rp][1]);
            acc[rp][2] = ffma2(ap[rp], b2, acc[rp][2]);
            acc[rp][3] = ffma2(ap[rp], b3, acc[rp][3]);
        }
    }
}

// prod[j][q] *= sigmoid(acc + bias), cols 4*lane+q
static __device__ __forceinline__ void fprod_sig(const ull (&acc)[4][4],
                                                 float (&prod)[8][4],
                                                 const float* __restrict__ bias, int lane)
{
    const float4 bb = *(const float4*)(bias + 4 * lane);
    const float bq[4] = {bb.x, bb.y, bb.z, bb.w};
    #pragma unroll
    for (int rp = 0; rp < 4; ++rp)
        #pragma unroll
        for (int q = 0; q < 4; ++q) {
            float lo, hi; upk2(acc[rp][q], lo, hi);
            prod[2 * rp][q]     *= fsig(lo + bq[q]);
            prod[2 * rp + 1][q] *= fsig(hi + bq[q]);
        }
}

// relu(acc + bias) -> transposed/swizzled As (overwrites ht planes 0..127)
static __device__ __forceinline__ void fepi_relu(const ull (&acc)[4][4], float* As,
                                                 const float* __restrict__ bias,
                                                 int rr, int lane)
{
    const float4 bb = *(const float4*)(bias + 4 * lane);
    const float bq[4] = {bb.x, bb.y, bb.z, bb.w};
    #pragma unroll
    for (int q = 0; q < 4; ++q) {
        const int c  = 4 * lane + q;
        const int s4 = ((c >> 3) & 7) << 2;
        float* col = As + c * AST2;
        #pragma unroll
        for (int rp = 0; rp < 4; ++rp) {
            float lo, hi; upk2(acc[rp][q], lo, hi);
            const int pr = (rr + 2 * rp) ^ s4;
            *(float2*)(col + pr) = make_float2(fmaxf(lo + bq[q], 0.f),
                                               fmaxf(hi + bq[q], 0.f));
        }
    }
}

// ---------------------------------------------------------------------------
// Fused per-key message kernel. grid = (ceil(E/64), K), 256 threads, 2 CTA/SM.
// ---------------------------------------------------------------------------
__global__ void __launch_bounds__(FTHR, 2)
gnn_fused_kernel(const float* __restrict__ h,
                 const int*   __restrict__ pairs,
                 const float* __restrict__ degrees,
                 const int*   __restrict__ scat,
                 const float* __restrict__ W_tr, const float* __restrict__ b_tr,
                 const float* __restrict__ W_g1, const float* __restrict__ b_g1,
                 const float* __restrict__ W_g2, const float* __restrict__ b_g2,
                 const float* __restrict__ eps,
                 float* __restrict__ out)
{
    extern __shared__ float sm[];
    float* As   = sm;                 // [131][AST2] ht, later g1 (transposed/swizzled)
    float* buf0 = As + F_AS;          // [66][128] weight K-half
    float* buf1 = buf0 + F_BUF;

    const int tid  = threadIdx.x;
    const int lane = tid & 31;
    const int rr   = (tid >> 5) * 8;  // warp-uniform row base (0..56)
    const int e0   = blockIdx.x * TR;
    const int k    = blockIdx.y;

    const float* Wtr = W_tr + (size_t)k * KD1 * D;
    const float* Wg1 = W_g1 + (size_t)k * KD1 * D;
    const float* Wg2 = W_g2 + (size_t)k * D * D;

    float prod[8][4];
    #pragma unroll
    for (int j = 0; j < 8; ++j)
        #pragma unroll
        for (int q = 0; q < 4; ++q) prod[j][q] = 1.0f;

    ull acc[4][4];

    for (int it = 0; it < NT; ++it) {
        __syncthreads();                     // prev-iter As reads done
        // gather ht tile (64 rows, 4 threads/row) + degree planes 128..130
        {
            const int r = tid >> 2, sub = tid & 3;
            const int e = e0 + r;
            int row = -1;
            if (e < NE) row = pairs[(k * NT + it) * NE + e];
            gather_rows<AST2>(As, h, row, r, sub);
            if (sub == 0) {                  // planes 128..130 have s4 = 0
                float d0 = 0.f, d1 = 0.f, d2 = 0.f;
                if (e < NE) {
                    const float* dg = degrees + ((size_t)(k * NT + it) * NE + e) * NOHL;
                    d0 = dg[0]; d1 = dg[1]; d2 = dg[2];
                }
                As[(D + 0) * AST2 + r] = d0;
                As[(D + 1) * AST2 + r] = d1;
                As[(D + 2) * AST2 + r] = d2;
            }
        }
        fillw(buf0, Wtr, 0, KH0, tid);
        cp_wait0(); __syncthreads();         // As + buf0 ready

        // GEMM tr, K-half 0 | fill tr half 1
        fillw(buf1, Wtr, KH0, KH1, tid);
        zacc(acc);
        fgemm<KH0>(As, buf0, 0, acc, rr, lane);
        cp_wait0(); __syncthreads();

        // GEMM tr, K-half 1 | fill g1 half 0
        fillw(buf0, Wg1, 0, KH0, tid);
        fgemm<KH1>(As, buf1, KH0, acc, rr, lane);
        fprod_sig(acc, prod, b_tr + k * D, lane);
        cp_wait0(); __syncthreads();

        // GEMM g1, K-half 0 | fill g1 half 1
        fillw(buf1, Wg1, KH0, KH1, tid);
        zacc(acc);
        fgemm<KH0>(As, buf0, 0, acc, rr, lane);
        cp_wait0(); __syncthreads();

        // GEMM g1, K-half 1 | fill g2 half 0
        fillw(buf0, Wg2, 0, 64, tid);
        fgemm<KH1>(As, buf1, KH0, acc, rr, lane);
        __syncthreads();                     // ALL ht reads complete
        fepi_relu(acc, As, b_g1 + k * D, rr, lane);   // g1 -> As in place
        cp_wait0(); __syncthreads();         // g1 visible + buf0 ready

        // GEMM g2, K-half 0 | fill g2 half 1
        fillw(buf1, Wg2, 64, 64, tid);
        zacc(acc);
        fgemm<64>(As, buf0, 0, acc, rr, lane);
        cp_wait0(); __syncthreads();

        // GEMM g2, K-half 1
        fgemm<64>(As, buf1, 64, acc, rr, lane);
        fprod_sig(acc, prod, b_g2 + k * D, lane);
    }

    // scatter-add: out[scat[k,e]] += (1+eps[k]) * prod ; cols 4*lane..+3
    const float scale = 1.0f + eps[k];
    #pragma unroll
    for (int j = 0; j < 8; ++j) {
        const int e = e0 + rr + j;
        if (e < NE) {
            const int idx = scat[k * NE + e];
            float* dst = out + (size_t)idx * D + 4 * lane;
            asm volatile("red.global.add.v4.f32 [%0], {%1,%2,%3,%4};"
                         :: "l"(dst),
                            "f"(prod[j][0] * scale), "f"(prod[j][1] * scale),
                            "f"(prod[j][2] * scale), "f"(prod[j][3] * scale) : "memory");
        }
    }
}

// ============================ lin kernel (R6-proven) ============================

static __device__ __forceinline__ void lfill_half(float* dst, const float* __restrict__ W,
                                                  int half, int tid)
{
    const unsigned d0 = (unsigned)__cvta_generic_to_shared(dst);
    const int n = D * 16;
    for (int i = tid; i < n; i += LTHR) {
        const int kk = i >> 4, c = i & 15;
        cp16(d0 + (unsigned)(kk * 64 + c * 4) * 4u, W + kk * D + half * 64 + c * 4);
    }
    cp_commit();
}

static __device__ __forceinline__ void lgemm(const float* __restrict__ A,
                                             const float* __restrict__ Wh,
                                             ull (&acc)[4][2], int rr, int lane)
{
    #pragma unroll
    for (int rp = 0; rp < 4; ++rp) { acc[rp][0] = 0ull; acc[rp][1] = 0ull; }
    #pragma unroll 4
    for (int kk = 0; kk < D; ++kk) {
        const int s4 = ((kk >> 3) & 7) << 2;
        const float* Ar = A + kk * LAST;
        const ulonglong2 alo = *(const ulonglong2*)(Ar + (rr ^ s4));
        const ulonglong2 ahi = *(const ulonglong2*)(Ar + ((rr + 4) ^ s4));
        const float2 b = *(const float2*)(Wh + kk * 64 + 2 * lane);
        const ull b0 = dup2(b.x), b1 = dup2(b.y);
        const ull ap[4] = {alo.x, alo.y, ahi.x, ahi.y};
        #pragma unroll
        for (int rp = 0; rp < 4; ++rp) {
            acc[rp][0] = ffma2(ap[rp], b0, acc[rp][0]);
            acc[rp][1] = ffma2(ap[rp], b1, acc[rp][1]);
        }
    }
}

__global__ void __launch_bounds__(LTHR, 1)
gnn_lin_kernel(const float* __restrict__ h, const float* __restrict__ W,
               const float* __restrict__ b, float* __restrict__ out)
{
    extern __shared__ float sm[];
    float* As   = sm;                  // [D][LAST]
    float* buf0 = As + L_AS;           // [D][64]
    float* buf1 = buf0 + L_BUF;

    const int tid  = threadIdx.x;
    const int lane = tid & 31;
    const int rr   = (tid >> 5) * 8;
    const int r0   = blockIdx.x * LTILE;

    {
        const int r = tid >> 2, sub = tid & 3;
        const int row = r0 + r;
        gather_rows<LAST>(As, h, row < NN ? row : -1, r, sub);
    }
    lfill_half(buf0, W, 0, tid);
    cp_wait0();
    __syncthreads();

    ull acc[4][2];
    #pragma unroll
    for (int hh = 0; hh < 2; ++hh) {
        if (hh == 0) lfill_half(buf1, W, 1, tid);
        lgemm(As, hh ? buf1 : buf0, acc, rr, lane);
        const float2 bb = *(const float2*)(b + 64 * hh + 2 * lane);
        #pragma unroll
        for (int rp = 0; rp < 4; ++rp) {
            float l0, h0, l1, h1;
            upk2(acc[rp][0], l0, h0);
            upk2(acc[rp][1], l1, h1);
            const int row = r0 + rr + 2 * rp;
            if (row < NN)
                *(float2*)(out + (size_t)row * D + 64 * hh + 2 * lane) =
                    make_float2(l0 + bb.x, l1 + bb.y);
            if (row + 1 < NN)
                *(float2*)(out + (size_t)(row + 1) * D + 64 * hh + 2 * lane) =
                    make_float2(h0 + bb.x, h1 + bb.y);
        }
        if (hh == 0) { cp_wait0(); __syncthreads(); }
    }
}

// ---------------------------------------------------------------------------
extern "C" void kernel_launch(void* const* d_in, const int* in_sizes, int n_in,
                              void* d_out, int out_size)
{
    const float* h       = (const float*)d_in[0];
    const int*   pairs   = (const int*)  d_in[1];
    const float* degrees = (const float*)d_in[2];
    const int*   scat    = (const int*)  d_in[3];
    const float* W_lin   = (const float*)d_in[4];
    const float* b_lin   = (const float*)d_in[5];
    const float* W_tr    = (const float*)d_in[6];
    const float* b_tr    = (const float*)d_in[7];
    const float* W_g1    = (const float*)d_in[8];
    const float* b_g1    = (const float*)d_in[9];
    const float* W_g2    = (const float*)d_in[10];
    const float* b_g2    = (const float*)d_in[11];
    const float* eps     = (const float*)d_in[12];
    float* out = (float*)d_out;

    cudaFuncSetAttribute(gnn_lin_kernel,
                         cudaFuncAttributeMaxDynamicSharedMemorySize, SM_L);
    cudaFuncSetAttribute(gnn_fused_kernel,
                         cudaFuncAttributeMaxDynamicSharedMemorySize, SM_F);

    gnn_lin_kernel<<<(NN + LTILE - 1) / LTILE, LTHR, SM_L>>>(h, W_lin, b_lin, out);

    dim3 grid((NE + TR - 1) / TR, NK);
    gnn_fused_kernel<<<grid, FTHR, SM_F>>>(h, pairs, degrees, scat,
                                           W_tr, b_tr, W_g1, b_g1,
                                           W_g2, b_g2, eps, out);
}

// round 9
// speedup vs baseline: 1.2364x; 1.0003x over previous
#include <cuda_runtime.h>
#include <cstdint>

#define NN    50000
#define D     128
#define NK    4
#define NT    2
#define NE    100000
#define NOHL  3
#define KD1   (D + NOHL)     // 131
#define KH0   66
#define KH1   65

// ---- fused kernel geometry: 64-row tiles, 256 threads, 2 CTAs/SM ----
#define TR    64             // pair rows per fused CTA
#define AST2  68             // fused As row stride (floats)
#define FTHR  256
#define F_AS  (KD1 * AST2)   // 8908 floats
#define F_BUF (KH0 * D)      // 8448 floats
#define SM_F  ((F_AS + 2 * F_BUF) * 4)   // 103216 B

// ---- lin kernel geometry (R6-proven): 128-row tiles, 512 threads ----
#define LTILE 128
#define LAST  132
#define LTHR  512
#define L_AS  (D * LAST)
#define L_BUF (D * 64)
#define SM_L  ((L_AS + 2 * L_BUF) * 4)   // 133120 B

typedef unsigned long long ull;

static __device__ __forceinline__ float fsig(float x) {
    return 1.0f / (1.0f + __expf(-x));
}
static __device__ __forceinline__ ull dup2(float v) {
    ull r; asm("mov.b64 %0, {%1, %1};" : "=l"(r) : "f"(v)); return r;
}
static __device__ __forceinline__ void upk2(ull v, float &lo, float &hi) {
    asm("mov.b64 {%0, %1}, %2;" : "=f"(lo), "=f"(hi) : "l"(v));
}
static __device__ __forceinline__ ull ffma2(ull a, ull b, ull c) {
    ull d; asm("fma.rn.f32x2 %0, %1, %2, %3;" : "=l"(d) : "l"(a), "l"(b), "l"(c));
    return d;
}
static __device__ __forceinline__ void cp16(unsigned s, const void* g) {
    asm volatile("cp.async.cg.shared.global [%0], [%1], 16;" :: "r"(s), "l"(g));
}
static __device__ __forceinline__ void cp_commit() {
    asm volatile("cp.async.commit_group;" ::: "memory");
}
static __device__ __forceinline__ void cp_wait0() {
    asm volatile("cp.async.wait_group 0;" ::: "memory");
}

// gather one tile row of h into transposed/swizzled As (stride STR). 4 thr/row.
template<int STR>
static __device__ __forceinline__ void gather_rows(float* As, const float* __restrict__ h,
                                                   int row, int r, int sub)
{
    if (row >= 0) {
        const float4* hrow = (const float4*)(h + (size_t)row * D) + 8 * sub;
        #pragma unroll
        for (int q = 0; q < 8; ++q) {
            const float4 v = hrow[q];
            const int c  = 32 * sub + 4 * q;
            const int pr = r ^ (((c >> 3) & 7) << 2);
            float* dst = As + c * STR + pr;
            dst[0] = v.x; dst[STR] = v.y; dst[2 * STR] = v.z; dst[3 * STR] = v.w;
        }
    } else {
        #pragma unroll
        for (int q = 0; q < 8; ++q) {
            const int c  = 32 * sub + 4 * q;
            const int pr = r ^ (((c >> 3) & 7) << 2);
            float* dst = As + c * STR + pr;
            dst[0] = 0.f; dst[STR] = 0.f; dst[2 * STR] = 0.f; dst[3 * STR] = 0.f;
        }
    }
}

// ============================ fused kernel helpers ============================

// contiguous weight rows [k0, k0+KH) of a [*][128] matrix -> smem [KH][128]
static __device__ __forceinline__ void fillw(float* dst, const float* __restrict__ W,
                                             int k0, int KH, int tid)
{
    const unsigned d0 = (unsigned)__cvta_generic_to_shared(dst);
    const char* src = (const char*)(W + (size_t)k0 * D);
    const int n = KH * 32;                       // 16B chunks (32 per 128-float row)
    for (int i = tid; i < n; i += FTHR)
        cp16(d0 + (unsigned)i * 16u, src + (size_t)i * 16);
    cp_commit();
}

static __device__ __forceinline__ void zacc(ull (&acc)[4][4]) {
    #pragma unroll
    for (int rp = 0; rp < 4; ++rp)
        #pragma unroll
        for (int q = 0; q < 4; ++q) acc[rp][q] = 0ull;
}

// partial-K GEMM pass: A transposed/swizzled [131][AST2], Wh [KH][128] smem.
// Thread: rows rr..rr+7 (rr warp-uniform), cols 4*lane..4*lane+3.
template<int KH>
static __device__ __forceinline__ void fgemm(const float* __restrict__ As,
                                             const float* __restrict__ Wh,
                                             int k0, ull (&acc)[4][4],
                                             int rr, int lane)
{
    #pragma unroll 4
    for (int kk = 0; kk < KH; ++kk) {
        const int kg = k0 + kk;
        const int s4 = ((kg >> 3) & 7) << 2;
        const float* Ar = As + kg * AST2;
        const ulonglong2 alo = *(const ulonglong2*)(Ar + (rr ^ s4));
        const ulonglong2 ahi = *(const ulonglong2*)(Ar + ((rr + 4) ^ s4));
        const float4 b = *(const float4*)(Wh + kk * D + 4 * lane);
        const ull b0 = dup2(b.x), b1 = dup2(b.y), b2 = dup2(b.z), b3 = dup2(b.w);
        const ull ap[4] = {alo.x, alo.y, ahi.x, ahi.y};
        #pragma unroll
        for (int rp = 0; rp < 4; ++rp) {
            acc[rp][0] = ffma2(ap[rp], b0, acc[rp][0]);
            acc[rp][1] = ffma2(ap[rp], b1, acc[rp][1]);
            acc[rp][2] = ffma2(ap[rp], b2, acc[rp][2]);
            acc[rp][3] = ffma2(ap[rp], b3, acc[rp][3]);
        }
    }
}

// prod[j][q] *= sigmoid(acc + bias), cols 4*lane+q
static __device__ __forceinline__ void fprod_sig(const ull (&acc)[4][4],
                                                 float (&prod)[8][4],
                                                 const float* __restrict__ bias, int lane)
{
    const float4 bb = *(const float4*)(bias + 4 * lane);
    const float bq[4] = {bb.x, bb.y, bb.z, bb.w};
    #pragma unroll
    for (int rp = 0; rp < 4; ++rp)
        #pragma unroll
        for (int q = 0; q < 4; ++q) {
            float lo, hi; upk2(acc[rp][q], lo, hi);
            prod[2 * rp][q]     *= fsig(lo + bq[q]);
            prod[2 * rp + 1][q] *= fsig(hi + bq[q]);
        }
}

// relu(acc + bias) -> transposed/swizzled As (overwrites ht planes 0..127)
static __device__ __forceinline__ void fepi_relu(const ull (&acc)[4][4], float* As,
                                                 const float* __restrict__ bias,
                                                 int rr, int lane)
{
    const float4 bb = *(const float4*)(bias + 4 * lane);
    const float bq[4] = {bb.x, bb.y, bb.z, bb.w};
    #pragma unroll
    for (int q = 0; q < 4; ++q) {
        const int c  = 4 * lane + q;
        const int s4 = ((c >> 3) & 7) << 2;
        float* col = As + c * AST2;
        #pragma unroll
        for (int rp = 0; rp < 4; ++rp) {
            float lo, hi; upk2(acc[rp][q], lo, hi);
            const int pr = (rr + 2 * rp) ^ s4;
            *(float2*)(col + pr) = make_float2(fmaxf(lo + bq[q], 0.f),
                                               fmaxf(hi + bq[q], 0.f));
        }
    }
}

// ---------------------------------------------------------------------------
// Fused per-key message kernel. grid = (ceil(E/64), K), 256 threads, 2 CTA/SM.
// ---------------------------------------------------------------------------
__global__ void __launch_bounds__(FTHR, 2)
gnn_fused_kernel(const float* __restrict__ h,
                 const int*   __restrict__ pairs,
                 const float* __restrict__ degrees,
                 const int*   __restrict__ scat,
                 const float* __restrict__ W_tr, const float* __restrict__ b_tr,
                 const float* __restrict__ W_g1, const float* __restrict__ b_g1,
                 const float* __restrict__ W_g2, const float* __restrict__ b_g2,
                 const float* __restrict__ eps,
                 float* __restrict__ out)
{
    extern __shared__ float sm[];
    float* As   = sm;                 // [131][AST2] ht, later g1 (transposed/swizzled)
    float* buf0 = As + F_AS;          // [66][128] weight K-half
    float* buf1 = buf0 + F_BUF;

    const int tid  = threadIdx.x;
    const int lane = tid & 31;
    const int rr   = (tid >> 5) * 8;  // warp-uniform row base (0..56)
    const int e0   = blockIdx.x * TR;
    const int k    = blockIdx.y;

    const float* Wtr = W_tr + (size_t)k * KD1 * D;
    const float* Wg1 = W_g1 + (size_t)k * KD1 * D;
    const float* Wg2 = W_g2 + (size_t)k * D * D;

    float prod[8][4];
    #pragma unroll
    for (int j = 0; j < 8; ++j)
        #pragma unroll
        for (int q = 0; q < 4; ++q) prod[j][q] = 1.0f;

    ull acc[4][4];

    for (int it = 0; it < NT; ++it) {
        __syncthreads();                     // prev-iter As reads done
        // gather ht tile (64 rows, 4 threads/row) + degree planes 128..130
        {
            const int r = tid >> 2, sub = tid & 3;
            const int e = e0 + r;
            int row = -1;
            if (e < NE) row = pairs[(k * NT + it) * NE + e];
            gather_rows<AST2>(As, h, row, r, sub);
            if (sub == 0) {                  // planes 128..130 have s4 = 0
                float d0 = 0.f, d1 = 0.f, d2 = 0.f;
                if (e < NE) {
                    const float* dg = degrees + ((size_t)(k * NT + it) * NE + e) * NOHL;
                    d0 = dg[0]; d1 = dg[1]; d2 = dg[2];
                }
                As[(D + 0) * AST2 + r] = d0;
                As[(D + 1) * AST2 + r] = d1;
                As[(D + 2) * AST2 + r] = d2;
            }
        }
        fillw(buf0, Wtr, 0, KH0, tid);
        cp_wait0(); __syncthreads();         // As + buf0 ready

        // GEMM tr, K-half 0 | fill tr half 1
        fillw(buf1, Wtr, KH0, KH1, tid);
        zacc(acc);
        fgemm<KH0>(As, buf0, 0, acc, rr, lane);
        cp_wait0(); __syncthreads();

        // GEMM tr, K-half 1 | fill g1 half 0
        fillw(buf0, Wg1, 0, KH0, tid);
        fgemm<KH1>(As, buf1, KH0, acc, rr, lane);
        fprod_sig(acc, prod, b_tr + k * D, lane);
        cp_wait0(); __syncthreads();

        // GEMM g1, K-half 0 | fill g1 half 1
        fillw(buf1, Wg1, KH0, KH1, tid);
        zacc(acc);
        fgemm<KH0>(As, buf0, 0, acc, rr, lane);
        cp_wait0(); __syncthreads();

        // GEMM g1, K-half 1 | fill g2 half 0
        fillw(buf0, Wg2, 0, 64, tid);
        fgemm<KH1>(As, buf1, KH0, acc, rr, lane);
        __syncthreads();                     // ALL ht reads complete
        fepi_relu(acc, As, b_g1 + k * D, rr, lane);   // g1 -> As in place
        cp_wait0(); __syncthreads();         // g1 visible + buf0 ready

        // GEMM g2, K-half 0 | fill g2 half 1
        fillw(buf1, Wg2, 64, 64, tid);
        zacc(acc);
        fgemm<64>(As, buf0, 0, acc, rr, lane);
        cp_wait0(); __syncthreads();

        // GEMM g2, K-half 1
        fgemm<64>(As, buf1, 64, acc, rr, lane);
        fprod_sig(acc, prod, b_g2 + k * D, lane);
    }

    // scatter-add: out[scat[k,e]] += (1+eps[k]) * prod ; cols 4*lane..+3
    const float scale = 1.0f + eps[k];
    #pragma unroll
    for (int j = 0; j < 8; ++j) {
        const int e = e0 + rr + j;
        if (e < NE) {
            const int idx = scat[k * NE + e];
            float* dst = out + (size_t)idx * D + 4 * lane;
            asm volatile("red.global.add.v4.f32 [%0], {%1,%2,%3,%4};"
                         :: "l"(dst),
                            "f"(prod[j][0] * scale), "f"(prod[j][1] * scale),
                            "f"(prod[j][2] * scale), "f"(prod[j][3] * scale) : "memory");
        }
    }
}

// ============================ lin kernel (R6-proven) ============================

static __device__ __forceinline__ void lfill_half(float* dst, const float* __restrict__ W,
                                                  int half, int tid)
{
    const unsigned d0 = (unsigned)__cvta_generic_to_shared(dst);
    const int n = D * 16;
    for (int i = tid; i < n; i += LTHR) {
        const int kk = i >> 4, c = i & 15;
        cp16(d0 + (unsigned)(kk * 64 + c * 4) * 4u, W + kk * D + half * 64 + c * 4);
    }
    cp_commit();
}

static __device__ __forceinline__ void lgemm(const float* __restrict__ A,
                                             const float* __restrict__ Wh,
                                             ull (&acc)[4][2], int rr, int lane)
{
    #pragma unroll
    for (int rp = 0; rp < 4; ++rp) { acc[rp][0] = 0ull; acc[rp][1] = 0ull; }
    #pragma unroll 4
    for (int kk = 0; kk < D; ++kk) {
        const int s4 = ((kk >> 3) & 7) << 2;
        const float* Ar = A + kk * LAST;
        const ulonglong2 alo = *(const ulonglong2*)(Ar + (rr ^ s4));
        const ulonglong2 ahi = *(const ulonglong2*)(Ar + ((rr + 4) ^ s4));
        const float2 b = *(const float2*)(Wh + kk * 64 + 2 * lane);
        const ull b0 = dup2(b.x), b1 = dup2(b.y);
        const ull ap[4] = {alo.x, alo.y, ahi.x, ahi.y};
        #pragma unroll
        for (int rp = 0; rp < 4; ++rp) {
            acc[rp][0] = ffma2(ap[rp], b0, acc[rp][0]);
            acc[rp][1] = ffma2(ap[rp], b1, acc[rp][1]);
        }
    }
}

__global__ void __launch_bounds__(LTHR, 1)
gnn_lin_kernel(const float* __restrict__ h, const float* __restrict__ W,
               const float* __restrict__ b, float* __restrict__ out)
{
    extern __shared__ float sm[];
    float* As   = sm;                  // [D][LAST]
    float* buf0 = As + L_AS;           // [D][64]
    float* buf1 = buf0 + L_BUF;

    const int tid  = threadIdx.x;
    const int lane = tid & 31;
    const int rr   = (tid >> 5) * 8;
    const int r0   = blockIdx.x * LTILE;

    {
        const int r = tid >> 2, sub = tid & 3;
        const int row = r0 + r;
        gather_rows<LAST>(As, h, row < NN ? row : -1, r, sub);
    }
    lfill_half(buf0, W, 0, tid);
    cp_wait0();
    __syncthreads();

    ull acc[4][2];
    #pragma unroll
    for (int hh = 0; hh < 2; ++hh) {
        if (hh == 0) lfill_half(buf1, W, 1, tid);
        lgemm(As, hh ? buf1 : buf0, acc, rr, lane);
        const float2 bb = *(const float2*)(b + 64 * hh + 2 * lane);
        #pragma unroll
        for (int rp = 0; rp < 4; ++rp) {
            float l0, h0, l1, h1;
            upk2(acc[rp][0], l0, h0);
            upk2(acc[rp][1], l1, h1);
            const int row = r0 + rr + 2 * rp;
            if (row < NN)
                *(float2*)(out + (size_t)row * D + 64 * hh + 2 * lane) =
                    make_float2(l0 + bb.x, l1 + bb.y);
            if (row + 1 < NN)
                *(float2*)(out + (size_t)(row + 1) * D + 64 * hh + 2 * lane) =
                    make_float2(h0 + bb.x, h1 + bb.y);
        }
        if (hh == 0) { cp_wait0(); __syncthreads(); }
    }
}

// ---------------------------------------------------------------------------
extern "C" void kernel_launch(void* const* d_in, const int* in_sizes, int n_in,
                              void* d_out, int out_size)
{
    const float* h       = (const float*)d_in[0];
    const int*   pairs   = (const int*)  d_in[1];
    const float* degrees = (const float*)d_in[2];
    const int*   scat    = (const int*)  d_in[3];
    const float* W_lin   = (const float*)d_in[4];
    const float* b_lin   = (const float*)d_in[5];
    const float* W_tr    = (const float*)d_in[6];
    const float* b_tr    = (const float*)d_in[7];
    const float* W_g1    = (const float*)d_in[8];
    const float* b_g1    = (const float*)d_in[9];
    const float* W_g2    = (const float*)d_in[10];
    const float* b_g2    = (const float*)d_in[11];
    const float* eps     = (const float*)d_in[12];
    float* out = (float*)d_out;

    cudaFuncSetAttribute(gnn_lin_kernel,
                         cudaFuncAttributeMaxDynamicSharedMemorySize, SM_L);
    cudaFuncSetAttribute(gnn_fused_kernel,
                         cudaFuncAttributeMaxDynamicSharedMemorySize, SM_F);

    gnn_lin_kernel<<<(NN + LTILE - 1) / LTILE, LTHR, SM_L>>>(h, W_lin, b_lin, out);

    dim3 grid((NE + TR - 1) / TR, NK);
    gnn_fused_kernel<<<grid, FTHR, SM_F>>>(h, pairs, degrees, scat,
                                           W_tr, b_tr, W_g1, b_g1,
                                           W_g2, b_g2, eps, out);
}

// round 12
// speedup vs baseline: 2.6941x; 2.1790x over previous
#include <cuda_runtime.h>
#include <cuda_bf16.h>
#include <cstdint>

#define NN 50000
#define D 128
#define NK 4
#define NT 2
#define NE 100000
#define NOHL 3
#define KD1 131
typedef unsigned long long ull;

// ---------------- helpers ----------------
static __device__ __forceinline__ uint32_t stou(const void* p){
    uint32_t a; asm("{ .reg .u64 t; cvta.to.shared.u64 t, %1; cvt.u32.u64 %0, t; }"
                    : "=r"(a) : "l"(p)); return a;
}
static __device__ __forceinline__ float sigf(float x){
    float e, r;
    asm("ex2.approx.f32 %0, %1;" : "=f"(e) : "f"(x * -1.44269504089f));
    asm("rcp.approx.f32 %0, %1;" : "=f"(r) : "f"(1.0f + e));
    return r;
}
static __device__ __forceinline__ uint32_t pkbf(float lo, float hi){
    uint32_t r; asm("cvt.rn.bf16x2.f32 %0, %1, %2;" : "=r"(r) : "f"(hi), "f"(lo)); return r;
}
static __device__ __forceinline__ void bfsplit(float x, float y, uint32_t& hi, uint32_t& lo){
    hi = pkbf(x, y);
    float xh = __uint_as_float(hi << 16);
    float yh = __uint_as_float(hi & 0xFFFF0000u);
    lo = pkbf(x - xh, y - yh);
}
static __device__ __forceinline__ uint32_t sw128(uint32_t o){ return o ^ ((o >> 3) & 0x70); }
static __device__ __forceinline__ void cp16(unsigned s, const void* g){
    asm volatile("cp.async.cg.shared.global [%0], [%1], 16;" :: "r"(s), "l"(g));
}
static __device__ __forceinline__ void cp_commit(){ asm volatile("cp.async.commit_group;" ::: "memory"); }
static __device__ __forceinline__ void cp_wait0(){ asm volatile("cp.async.wait_group 0;" ::: "memory"); }

#define MMA(d, a, b) asm volatile( \
    "mma.sync.aligned.m16n8k16.row.col.f32.bf16.bf16.f32 " \
    "{%0,%1,%2,%3}, {%4,%5,%6,%7}, {%8,%9}, {%0,%1,%2,%3};" \
    : "+f"((d)[0]), "+f"((d)[1]), "+f"((d)[2]), "+f"((d)[3]) \
    : "r"((a)[0]), "r"((a)[1]), "r"((a)[2]), "r"((a)[3]), "r"((b).x), "r"((b).y))
#define LDSM4(r, a) asm volatile( \
    "ldmatrix.sync.aligned.m8n8.x4.shared.b16 {%0,%1,%2,%3}, [%4];" \
    : "=r"((r)[0]), "=r"((r)[1]), "=r"((r)[2]), "=r"((r)[3]) : "r"(a))

// ---------------- prepped B fragments ----------------
// layout: [mat(12)][term(2)][kt(8)*16+gnt(16)][lane(32)] of uint2 (b0,b1)
__device__ uint2 g_Bf[12 * 2 * 4096];

__global__ void prep_kernel(const float* __restrict__ Wtr, const float* __restrict__ Wg1,
                            const float* __restrict__ Wg2){
    int id = blockIdx.x * 256 + threadIdx.x;     // [12][8][16][32]
    if (id >= 12 * 8 * 16 * 32) return;
    int lane = id & 31, nt = (id >> 5) & 15, kt = (id >> 9) & 7, mat = id >> 12;
    int kk = mat / 3, m = mat % 3;
    const float* W = (m == 0) ? Wtr + (size_t)kk * KD1 * D
                   : (m == 1) ? Wg1 + (size_t)kk * KD1 * D
                              : Wg2 + (size_t)kk * D * D;
    int k0 = kt * 16 + (lane & 3) * 2;
    int n  = nt * 8 + (lane >> 2);
    uint32_t h0, l0, h1, l1;
    bfsplit(W[(size_t)k0 * D + n], W[(size_t)(k0 + 1) * D + n], h0, l0);
    bfsplit(W[(size_t)(k0 + 8) * D + n], W[(size_t)(k0 + 9) * D + n], h1, l1);
    int fo = (kt * 16 + nt) * 32 + lane;
    g_Bf[(mat * 2 + 0) * 4096 + fo] = make_uint2(h0, h1);
    g_Bf[(mat * 2 + 1) * 4096 + fo] = make_uint2(l0, l1);
}

// ---------------- smem map ----------------
#define O_AH 0
#define O_AL 32768
#define O_DEG 65536          // float4[128]
#define O_DEGW 67584         // float[2][3][128]
#define O_BIAS 70656         // float[3][128]
#define SM_MMA 72192

// 3-term split-bf16 GEMM: 128x128x128, acc[16][4] fp32
static __device__ __forceinline__ void do_gemm(float (*acc)[4], uint32_t aH, uint32_t aL,
                                               const uint2* __restrict__ BfH,
                                               const uint2* __restrict__ BfL,
                                               int wr, int wc, int lane)
{
    #pragma unroll
    for (int i = 0; i < 16; ++i)
        #pragma unroll
        for (int j = 0; j < 4; ++j) acc[i][j] = 0.f;

    #pragma unroll 1
    for (int kt = 0; kt < 8; ++kt) {
        uint32_t ah[4][4], al[4][4];
        const int row = wr * 64 + (lane & 15);
        const int kk  = kt * 16 + (lane >> 4) * 8;
        const uint32_t soff = (uint32_t)(kk >> 6) * 16384u;
        #pragma unroll
        for (int mt = 0; mt < 4; ++mt) {
            uint32_t a = soff + sw128((uint32_t)((row + mt * 16) * 128 + (kk & 63) * 2));
            LDSM4(ah[mt], aH + a);
            LDSM4(al[mt], aL + a);
        }
        uint2 bh[4], bl[4];
        #pragma unroll
        for (int nt = 0; nt < 4; ++nt) {
            int fo = (kt * 16 + wc * 4 + nt) * 32 + lane;
            bh[nt] = __ldg(BfH + fo);
            bl[nt] = __ldg(BfL + fo);
        }
        #pragma unroll
        for (int mt = 0; mt < 4; ++mt)
            #pragma unroll
            for (int nt = 0; nt < 4; ++nt) {
                float* d = acc[mt * 4 + nt];
                MMA(d, ah[mt], bh[nt]);
                MMA(d, ah[mt], bl[nt]);
                MMA(d, al[mt], bh[nt]);
            }
    }
}

// epilogue: MODE 0 = sigmoid*prod (tr, deg), 1 = relu->A bf16 (g1, deg), 2 = sigmoid*prod (g2)
template<int MODE>
static __device__ __forceinline__ void epi(float (*acc)[4], float* prod,
                                           const float4* DEG, const float* DEGW,
                                           const float* BIAS,
                                           int wr, int wc, int lane, char* AH, char* AL)
{
    const float* BW = DEGW + (MODE == 1 ? 384 : 0);
    #pragma unroll
    for (int mt = 0; mt < 4; ++mt) {
        const int r0 = wr * 64 + mt * 16 + (lane >> 2);
        float4 dva, dvb;
        if (MODE != 2) { dva = DEG[r0]; dvb = DEG[r0 + 8]; }
        #pragma unroll
        for (int nt = 0; nt < 4; ++nt) {
            const int c0 = wc * 32 + nt * 8 + 2 * (lane & 3);
            const float b0 = BIAS[MODE * 128 + c0], b1 = BIAS[MODE * 128 + c0 + 1];
            float* a = acc[mt * 4 + nt];
            float x0 = a[0] + b0, x1 = a[1] + b1, x2 = a[2] + b0, x3 = a[3] + b1;
            if (MODE != 2) {
                float w00 = BW[c0], w01 = BW[c0 + 1];
                float w10 = BW[128 + c0], w11 = BW[128 + c0 + 1];
                float w20 = BW[256 + c0], w21 = BW[256 + c0 + 1];
                x0 += dva.x * w00 + dva.y * w10 + dva.z * w20;
                x1 += dva.x * w01 + dva.y * w11 + dva.z * w21;
                x2 += dvb.x * w00 + dvb.y * w10 + dvb.z * w20;
                x3 += dvb.x * w01 + dvb.y * w11 + dvb.z * w21;
            }
            if (MODE == 1) {
                uint32_t hi, lo;
                uint32_t oa = (uint32_t)(c0 >> 6) * 16384u + sw128((uint32_t)(r0 * 128 + (c0 & 63) * 2));
                bfsplit(fmaxf(x0, 0.f), fmaxf(x1, 0.f), hi, lo);
                *(uint32_t*)(AH + oa) = hi; *(uint32_t*)(AL + oa) = lo;
                uint32_t ob = (uint32_t)(c0 >> 6) * 16384u + sw128((uint32_t)((r0 + 8) * 128 + (c0 & 63) * 2));
                bfsplit(fmaxf(x2, 0.f), fmaxf(x3, 0.f), hi, lo);
                *(uint32_t*)(AH + ob) = hi; *(uint32_t*)(AL + ob) = lo;
            } else {
                float* p = prod + (mt * 4 + nt) * 4;
                p[0] *= sigf(x0); p[1] *= sigf(x1); p[2] *= sigf(x2); p[3] *= sigf(x3);
            }
        }
    }
}

// ---------------------------------------------------------------------------
// Fused warp-MMA kernel. grid = (ceil(E/128), K), 256 threads.
// ---------------------------------------------------------------------------
__global__ void __launch_bounds__(256)
gnn_mma_kernel(const float* __restrict__ h, const int* __restrict__ pairs,
               const float* __restrict__ degrees, const int* __restrict__ scat,
               const float* __restrict__ W_tr, const float* __restrict__ b_tr,
               const float* __restrict__ W_g1, const float* __restrict__ b_g1,
               const float* __restrict__ W_g2, const float* __restrict__ b_g2,
               const float* __restrict__ eps, float* __restrict__ out)
{
    extern __shared__ char smc[];
    char* AH = smc + O_AH;  char* AL = smc + O_AL;
    float4* DEG = (float4*)(smc + O_DEG);
    float* DEGW = (float*)(smc + O_DEGW);
    float* BIAS = (float*)(smc + O_BIAS);

    const int tid = threadIdx.x, lane = tid & 31, warp = tid >> 5;
    const int wr = warp >> 2, wc = warp & 3;
    const int e0 = blockIdx.x * 128, k = blockIdx.y;
    const uint32_t aHs = stou(AH), aLs = stou(AL);

    // constants: degree-weight rows 128..130 and biases
    for (int i = tid; i < 384; i += 256) {
        DEGW[i]       = W_tr[(size_t)k * KD1 * D + 128 * D + i];
        DEGW[384 + i] = W_g1[(size_t)k * KD1 * D + 128 * D + i];
    }
    if (tid < 128) {
        BIAS[tid]       = b_tr[k * D + tid];
        BIAS[128 + tid] = b_g1[k * D + tid];
        BIAS[256 + tid] = b_g2[k * D + tid];
    }

    const uint2* Bf = g_Bf;
    float prod[64];
    #pragma unroll
    for (int i = 0; i < 64; ++i) prod[i] = 1.0f;
    float acc[16][4];

    for (int it = 0; it < NT; ++it) {
        __syncthreads();                       // prior A reads done
        // ---- gather ht -> AH/AL (bf16 split, SW128 chunks), deg -> DEG ----
        {
            int r = tid >> 1, hf = tid & 1;
            int e = e0 + r;
            int row = (e < NE) ? pairs[(k * NT + it) * NE + e] : -1;
            const float4* src = (const float4*)(h + (size_t)(row < 0 ? 0 : row) * D) + hf * 16;
            #pragma unroll
            for (int q = 0; q < 16; ++q) {
                float4 v = (row >= 0) ? src[q] : make_float4(0.f, 0.f, 0.f, 0.f);
                int kd = hf * 64 + 4 * q;
                uint32_t h0, l0, h1, l1;
                bfsplit(v.x, v.y, h0, l0);
                bfsplit(v.z, v.w, h1, l1);
                uint32_t off = (uint32_t)hf * 16384u + sw128((uint32_t)(r * 128 + (kd & 63) * 2));
                *(uint2*)(AH + off) = make_uint2(h0, h1);
                *(uint2*)(AL + off) = make_uint2(l0, l1);
            }
            if (hf == 0) {
                float4 dv = make_float4(0.f, 0.f, 0.f, 0.f);
                if (e < NE) {
                    const float* dp = degrees + ((size_t)(k * NT + it) * NE + e) * NOHL;
                    dv.x = dp[0]; dv.y = dp[1]; dv.z = dp[2];
                }
                DEG[r] = dv;
            }
        }
        __syncthreads();

        // GEMM1: tr
        do_gemm(acc, aHs, aLs, Bf + ((k * 3 + 0) * 2 + 0) * 4096,
                               Bf + ((k * 3 + 0) * 2 + 1) * 4096, wr, wc, lane);
        epi<0>(acc, prod, DEG, DEGW, BIAS, wr, wc, lane, AH, AL);
        // GEMM2: g1 (reads same A)
        do_gemm(acc, aHs, aLs, Bf + ((k * 3 + 1) * 2 + 0) * 4096,
                               Bf + ((k * 3 + 1) * 2 + 1) * 4096, wr, wc, lane);
        __syncthreads();                       // all A reads complete
        epi<1>(acc, prod, DEG, DEGW, BIAS, wr, wc, lane, AH, AL);   // g1 -> A
        __syncthreads();
        // GEMM3: g2 over g1
        do_gemm(acc, aHs, aLs, Bf + ((k * 3 + 2) * 2 + 0) * 4096,
                               Bf + ((k * 3 + 2) * 2 + 1) * 4096, wr, wc, lane);
        epi<2>(acc, prod, DEG, DEGW, BIAS, wr, wc, lane, AH, AL);
    }

    // ---- scatter-add ----
    const float sc = 1.0f + __ldg(eps + k);
    #pragma unroll
    for (int mt = 0; mt < 4; ++mt)
        #pragma unroll
        for (int hr = 0; hr < 2; ++hr) {
            int r = wr * 64 + mt * 16 + (lane >> 2) + hr * 8;
            int e = e0 + r;
            if (e < NE) {
                int idx = __ldg(scat + k * NE + e);
                float* base = out + (size_t)idx * D;
                #pragma unroll
                for (int nt = 0; nt < 4; ++nt) {
                    int c0 = wc * 32 + nt * 8 + 2 * (lane & 3);
                    float v0 = prod[(mt * 4 + nt) * 4 + hr * 2] * sc;
                    float v1 = prod[(mt * 4 + nt) * 4 + hr * 2 + 1] * sc;
                    asm volatile("red.global.add.v2.f32 [%0], {%1,%2};"
                                 :: "l"(base + c0), "f"(v0), "f"(v1) : "memory");
                }
            }
        }
}

// ======================= lin kernel (R6-proven) =======================
#define LTILE 128
#define LAST  132
#define LTHR  512
#define L_AS  (D * LAST)
#define L_BUF (D * 64)
#define SM_L  ((L_AS + 2 * L_BUF) * 4)

static __device__ __forceinline__ ull dup2(float v){
    ull r; asm("mov.b64 %0, {%1, %1};" : "=l"(r) : "f"(v)); return r;
}
static __device__ __forceinline__ void upk2(ull v, float &lo, float &hi){
    asm("mov.b64 {%0, %1}, %2;" : "=f"(lo), "=f"(hi) : "l"(v));
}
static __device__ __forceinline__ ull ffma2(ull a, ull b, ull c){
    ull d; asm("fma.rn.f32x2 %0, %1, %2, %3;" : "=l"(d) : "l"(a), "l"(b), "l"(c));
    return d;
}
__global__ void __launch_bounds__(LTHR, 1)
gnn_lin_kernel(const float* __restrict__ h, const float* __restrict__ W,
               const float* __restrict__ b, float* __restrict__ out)
{
    extern __shared__ float sm[];
    float* As = sm; float* buf0 = As + L_AS; float* buf1 = buf0 + L_BUF;
    const int tid = threadIdx.x, lane = tid & 31, rr = (tid >> 5) * 8;
    const int r0 = blockIdx.x * LTILE;
    {
        int r = tid >> 2, sub = tid & 3, row = r0 + r;
        #pragma unroll
        for (int q = 0; q < 8; ++q) {
            const int c = 32 * sub + 4 * q;
            const int pr = r ^ (((c >> 3) & 7) << 2);
            float* dst = As + c * LAST + pr;
            if (row < NN) {
                const float4 v = ((const float4*)(h + (size_t)row * D))[8 * sub + q];
                dst[0] = v.x; dst[LAST] = v.y; dst[2 * LAST] = v.z; dst[3 * LAST] = v.w;
            } else { dst[0] = 0.f; dst[LAST] = 0.f; dst[2 * LAST] = 0.f; dst[3 * LAST] = 0.f; }
        }
    }
    {
        const unsigned d0 = (unsigned)__cvta_generic_to_shared(buf0);
        for (int i = tid; i < D * 16; i += LTHR) {
            const int kk = i >> 4, c = i & 15;
            cp16(d0 + (unsigned)(kk * 64 + c * 4) * 4u, W + kk * D + c * 4);
        }
        cp_commit();
    }
    cp_wait0(); __syncthreads();
    ull acc[4][2];
    #pragma unroll
    for (int hh = 0; hh < 2; ++hh) {
        if (hh == 0) {
            const unsigned d1 = (unsigned)__cvta_generic_to_shared(buf1);
            for (int i = tid; i < D * 16; i += LTHR) {
                const int kk = i >> 4, c = i & 15;
                cp16(d1 + (unsigned)(kk * 64 + c * 4) * 4u, W + kk * D + 64 + c * 4);
            }
            cp_commit();
        }
        #pragma unroll
        for (int rp = 0; rp < 4; ++rp) { acc[rp][0] = 0ull; acc[rp][1] = 0ull; }
        const float* Wh = hh ? buf1 : buf0;
        #pragma unroll 4
        for (int kk = 0; kk < D; ++kk) {
            const int s4 = ((kk >> 3) & 7) << 2;
            const float* Ar = As + kk * LAST;
            const ulonglong2 alo = *(const ulonglong2*)(Ar + (rr ^ s4));
            const ulonglong2 ahi = *(const ulonglong2*)(Ar + ((rr + 4) ^ s4));
            const float2 bv = *(const float2*)(Wh + kk * 64 + 2 * lane);
            const ull b0 = dup2(bv.x), b1 = dup2(bv.y);
            const ull ap[4] = {alo.x, alo.y, ahi.x, ahi.y};
            #pragma unroll
            for (int rp = 0; rp < 4; ++rp) {
                acc[rp][0] = ffma2(ap[rp], b0, acc[rp][0]);
                acc[rp][1] = ffma2(ap[rp], b1, acc[rp][1]);
            }
        }
        const float2 bb = *(const float2*)(b + 64 * hh + 2 * lane);
        #pragma unroll
        for (int rp = 0; rp < 4; ++rp) {
            float l0, h0, l1, h1;
            upk2(acc[rp][0], l0, h0); upk2(acc[rp][1], l1, h1);
            const int row = r0 + rr + 2 * rp;
            if (row < NN)
                *(float2*)(out + (size_t)row * D + 64 * hh + 2 * lane) = make_float2(l0 + bb.x, l1 + bb.y);
            if (row + 1 < NN)
                *(float2*)(out + (size_t)(row + 1) * D + 64 * hh + 2 * lane) = make_float2(h0 + bb.x, h1 + bb.y);
        }
        if (hh == 0) { cp_wait0(); __syncthreads(); }
    }
}

// ---------------------------------------------------------------------------
extern "C" void kernel_launch(void* const* d_in, const int* in_sizes, int n_in,
                              void* d_out, int out_size)
{
    const float* h       = (const float*)d_in[0];
    const int*   pairs   = (const int*)  d_in[1];
    const float* degrees = (const float*)d_in[2];
    const int*   scat    = (const int*)  d_in[3];
    const float* W_lin   = (const float*)d_in[4];
    const float* b_lin   = (const float*)d_in[5];
    const float* W_tr    = (const float*)d_in[6];
    const float* b_tr    = (const float*)d_in[7];
    const float* W_g1    = (const float*)d_in[8];
    const float* b_g1    = (const float*)d_in[9];
    const float* W_g2    = (const float*)d_in[10];
    const float* b_g2    = (const float*)d_in[11];
    const float* eps     = (const float*)d_in[12];
    float* out = (float*)d_out;

    cudaFuncSetAttribute(gnn_lin_kernel, cudaFuncAttributeMaxDynamicSharedMemorySize, SM_L);
    cudaFuncSetAttribute(gnn_mma_kernel, cudaFuncAttributeMaxDynamicSharedMemorySize, SM_MMA);

    prep_kernel<<<192, 256>>>(W_tr, W_g1, W_g2);
    gnn_lin_kernel<<<(NN + LTILE - 1) / LTILE, LTHR, SM_L>>>(h, W_lin, b_lin, out);
    dim3 grid((NE + 127) / 128, NK);
    gnn_mma_kernel<<<grid, 256, SM_MMA>>>(h, pairs, degrees, scat, W_tr, b_tr,
                                          W_g1, b_g1, W_g2, b_g2, eps, out);
}